// round 1
// baseline (speedup 1.0000x reference)
#include <cuda_runtime.h>

// HoloLinear: out[t][o] = sum_h ( sum_i x[t][i]*basis[h][i] ) * (amp[o][h]*cos(phase[o][h]))
// Decomposed: W = amp*cos(phase) [O,H]; R = x @ basis^T [T,H]; out = R @ W^T [T,O]
#define TOKENS 16384
#define INF    1024
#define HARM   32
#define OUTF   4096
#define HPAIR  16   // HARM/2 harmonic pairs (f32x2 packing)

// Scratch (device globals: no allocation allowed in kernel_launch)
__device__ float              g_R[TOKENS * HARM];            // 2 MB
__device__ unsigned long long g_Wp[HPAIR * OUTF];            // 512 KB, layout [hp][o], each = (W[o][2hp], W[o][2hp+1])

// ---------------------------------------------------------------------------
// Prep: W packed pairs, layout [hp][o] so step-3 loads are o-contiguous.
// ---------------------------------------------------------------------------
__global__ void prep_w_kernel(const float* __restrict__ phase,
                              const float* __restrict__ amp) {
    int idx = blockIdx.x * 256 + threadIdx.x;   // 0 .. HPAIR*OUTF-1
    int hp  = idx >> 12;                        // / OUTF
    int o   = idx & (OUTF - 1);
    int base = o * HARM + 2 * hp;
    float lo = amp[base]     * cosf(phase[base]);
    float hi = amp[base + 1] * cosf(phase[base + 1]);
    unsigned long long u;
    asm("mov.b64 %0, {%1, %2};" : "=l"(u) : "f"(lo), "f"(hi));
    g_Wp[idx] = u;
}

// ---------------------------------------------------------------------------
// Step 2: R = x @ basis^T.  M=16384, N=32, K=1024 fp32 GEMM.
// Block: 256 threads, tile 128 tokens x 32 harmonics, K-chunks of 32.
// Thread tile 4x4.
// ---------------------------------------------------------------------------
__global__ __launch_bounds__(256) void resonance_kernel(
    const float* __restrict__ x, const float* __restrict__ basis) {
    __shared__ float xs[128 * 33];  // pad 33 -> conflict-free column reads
    __shared__ float bs[32 * 33];

    int tid = threadIdx.x;
    int tb  = blockIdx.x * 128;
    int tg  = tid >> 3;   // 0..31 : token group (4 tokens each)
    int hg  = tid & 7;    // 0..7  : harmonic group (4 h each)

    float acc[4][4];
#pragma unroll
    for (int i = 0; i < 4; i++)
#pragma unroll
        for (int j = 0; j < 4; j++) acc[i][j] = 0.0f;

    for (int k0 = 0; k0 < INF; k0 += 32) {
        __syncthreads();
        // x tile: 128 rows x 32 floats  (1024 float4, 4 per thread)
#pragma unroll
        for (int r = 0; r < 4; r++) {
            int idx = tid + r * 256;
            int row = idx >> 3;
            int c4  = idx & 7;
            float4 v = *reinterpret_cast<const float4*>(
                &x[(long)(tb + row) * INF + k0 + c4 * 4]);
            float* d = &xs[row * 33 + c4 * 4];
            d[0] = v.x; d[1] = v.y; d[2] = v.z; d[3] = v.w;
        }
        // basis tile: 32 rows x 32 floats (256 float4, 1 per thread)
        {
            int row = tid >> 3;
            int c4  = tid & 7;
            float4 v = *reinterpret_cast<const float4*>(
                &basis[row * INF + k0 + c4 * 4]);
            float* d = &bs[row * 33 + c4 * 4];
            d[0] = v.x; d[1] = v.y; d[2] = v.z; d[3] = v.w;
        }
        __syncthreads();
#pragma unroll
        for (int kk = 0; kk < 32; kk++) {
            float a[4], b[4];
#pragma unroll
            for (int i = 0; i < 4; i++) a[i] = xs[(tg * 4 + i) * 33 + kk];
#pragma unroll
            for (int j = 0; j < 4; j++) b[j] = bs[(hg * 4 + j) * 33 + kk];
#pragma unroll
            for (int i = 0; i < 4; i++)
#pragma unroll
                for (int j = 0; j < 4; j++)
                    acc[i][j] = fmaf(a[i], b[j], acc[i][j]);
        }
    }
#pragma unroll
    for (int i = 0; i < 4; i++)
#pragma unroll
        for (int j = 0; j < 4; j++)
            g_R[(long)(tb + tg * 4 + i) * HARM + hg * 4 + j] = acc[i][j];
}

// ---------------------------------------------------------------------------
// Step 3: out = R @ W^T.  M=16384, N=4096, K=32 fp32, K packed as 16 f32x2.
// Block: 256 threads, tile 128 tokens x 128 outputs, per-thread 8x8.
// Thread (tg,og): tokens tg*8..+7, outputs og*2 + 32*j + c (j=0..3, c=0..1).
// All K resident in smem (no k-loop staging): Rs 128x16 pairs, Ws 16x128 pairs.
// ---------------------------------------------------------------------------
__global__ __launch_bounds__(256) void holo_out_kernel(float* __restrict__ out) {
    __shared__ unsigned long long Rs[128 * 17];  // [t][hp], pad 17
    __shared__ unsigned long long Ws[HPAIR * 128];  // [hp][o_local]

    int tid = threadIdx.x;
    int tb  = blockIdx.y * 128;
    int ob  = blockIdx.x * 128;

    const unsigned long long* gR =
        reinterpret_cast<const unsigned long long*>(g_R);
#pragma unroll
    for (int r = 0; r < 8; r++) {
        int idx = tid + r * 256;          // 0..2047
        int row = idx >> 4, hp = idx & 15;
        Rs[row * 17 + hp] = gR[(long)(tb + row) * HPAIR + hp];
    }
#pragma unroll
    for (int r = 0; r < 8; r++) {
        int idx = tid + r * 256;          // 0..2047
        int hp = idx >> 7, col = idx & 127;
        Ws[hp * 128 + col] = g_Wp[hp * OUTF + ob + col];
    }
    __syncthreads();

    int tg = tid >> 4;   // 0..15
    int og = tid & 15;   // 0..15

    unsigned long long acc[8][8];
#pragma unroll
    for (int i = 0; i < 8; i++)
#pragma unroll
        for (int j = 0; j < 8; j++) acc[i][j] = 0ULL;

#pragma unroll
    for (int hp = 0; hp < HPAIR; hp++) {
        unsigned long long rr[8];
        ulonglong2 ww[4];
#pragma unroll
        for (int i = 0; i < 8; i++) rr[i] = Rs[(tg * 8 + i) * 17 + hp];
#pragma unroll
        for (int j = 0; j < 4; j++)
            ww[j] = *reinterpret_cast<const ulonglong2*>(
                &Ws[hp * 128 + og * 2 + 32 * j]);
#pragma unroll
        for (int i = 0; i < 8; i++) {
#pragma unroll
            for (int j = 0; j < 4; j++) {
                asm("fma.rn.f32x2 %0, %1, %2, %0;"
                    : "+l"(acc[i][2 * j]) : "l"(rr[i]), "l"(ww[j].x));
                asm("fma.rn.f32x2 %0, %1, %2, %0;"
                    : "+l"(acc[i][2 * j + 1]) : "l"(rr[i]), "l"(ww[j].y));
            }
        }
    }

    // Epilogue: fold f32x2 partials, store float2 (coalesced across og).
#pragma unroll
    for (int i = 0; i < 8; i++) {
        long t = tb + tg * 8 + i;
#pragma unroll
        for (int j = 0; j < 4; j++) {
            float lo0, hi0, lo1, hi1;
            asm("mov.b64 {%0, %1}, %2;" : "=f"(lo0), "=f"(hi0)
                : "l"(acc[i][2 * j]));
            asm("mov.b64 {%0, %1}, %2;" : "=f"(lo1), "=f"(hi1)
                : "l"(acc[i][2 * j + 1]));
            float2 v = make_float2(lo0 + hi0, lo1 + hi1);
            *reinterpret_cast<float2*>(
                &out[t * OUTF + ob + og * 2 + 32 * j]) = v;
        }
    }
}

// ---------------------------------------------------------------------------
extern "C" void kernel_launch(void* const* d_in, const int* in_sizes, int n_in,
                              void* d_out, int out_size) {
    const float* x     = (const float*)d_in[0];  // [16384,1024]
    const float* basis = (const float*)d_in[1];  // [32,1024]
    const float* phase = (const float*)d_in[2];  // [4096,32]
    const float* amp   = (const float*)d_in[3];  // [4096,32]
    float* out = (float*)d_out;                  // [16384,4096]

    prep_w_kernel<<<(HPAIR * OUTF) / 256, 256>>>(phase, amp);
    resonance_kernel<<<TOKENS / 128, 256>>>(x, basis);
    dim3 gridC(OUTF / 128, TOKENS / 128);
    holo_out_kernel<<<gridC, 256>>>(out);
}

// round 3
// speedup vs baseline: 1.3968x; 1.3968x over previous
#include <cuda_runtime.h>
#include <cuda_bf16.h>
#include <cstdint>

// out[t][o] = sum_h R[t][h] * W[o][h],  R = x @ basis^T, W = amp*cos(phase)
// Step 3 on HMMA (mma.sync bf16) with split precision:
//   A = [R_hi | R_lo | R_hi]  (K=96 bf16),  B = [W_hi | W_hi | W_lo]
//   A.B^T = R_hi.W_hi + R_lo.W_hi + R_hi.W_lo ~= R.W  (residual ~1e-5)
#define TOKENS 16384
#define INF    1024
#define HARM   32
#define OUTF   4096
#define KSPL   96
#define KPAD   120   // smem row stride in bf16 (240 B): ldmatrix conflict-free

// Scratch device globals (no allocation allowed)
__device__ __align__(16) __nv_bfloat16 g_Rs[TOKENS * KSPL];  // 3 MB
__device__ __align__(16) __nv_bfloat16 g_Ws[OUTF * KSPL];    // 768 KB

__device__ __forceinline__ uint32_t smem_u32(const void* p) {
    uint32_t a;
    asm("{ .reg .u64 t; cvta.to.shared.u64 t, %1; cvt.u32.u64 %0, t; }"
        : "=r"(a) : "l"(p));
    return a;
}

// ---------------------------------------------------------------------------
// Prep: W = amp*cos(phase), bf16 split  [o][0:32)=hi, [32:64)=hi, [64:96)=lo
// ---------------------------------------------------------------------------
__global__ void prep_w_kernel(const float* __restrict__ phase,
                              const float* __restrict__ amp) {
    int idx = blockIdx.x * 256 + threadIdx.x;   // 0 .. OUTF*HARM-1
    int o = idx >> 5;
    int h = idx & 31;
    float w = amp[idx] * cosf(phase[idx]);
    __nv_bfloat16 hi = __float2bfloat16(w);
    __nv_bfloat16 lo = __float2bfloat16(w - __bfloat162float(hi));
    g_Ws[o * KSPL + h]      = hi;
    g_Ws[o * KSPL + 32 + h] = hi;
    g_Ws[o * KSPL + 64 + h] = lo;
}

// ---------------------------------------------------------------------------
// Step 2: R = x @ basis^T  (fp32 FFMA). Epilogue writes bf16 split:
//   [t][0:32)=hi, [32:64)=lo, [64:96)=hi
// ---------------------------------------------------------------------------
__global__ __launch_bounds__(256) void resonance_kernel(
    const float* __restrict__ x, const float* __restrict__ basis) {
    __shared__ float xs[128 * 33];
    __shared__ float bs[32 * 33];

    int tid = threadIdx.x;
    int tb  = blockIdx.x * 128;
    int tg  = tid >> 3;   // 0..31 token group (4 tokens)
    int hg  = tid & 7;    // 0..7  harmonic group (4 h)

    float acc[4][4];
#pragma unroll
    for (int i = 0; i < 4; i++)
#pragma unroll
        for (int j = 0; j < 4; j++) acc[i][j] = 0.0f;

    for (int k0 = 0; k0 < INF; k0 += 32) {
        __syncthreads();
#pragma unroll
        for (int r = 0; r < 4; r++) {
            int idx = tid + r * 256;
            int row = idx >> 3;
            int c4  = idx & 7;
            float4 v = *reinterpret_cast<const float4*>(
                &x[(long)(tb + row) * INF + k0 + c4 * 4]);
            float* d = &xs[row * 33 + c4 * 4];
            d[0] = v.x; d[1] = v.y; d[2] = v.z; d[3] = v.w;
        }
        {
            int row = tid >> 3;
            int c4  = tid & 7;
            float4 v = *reinterpret_cast<const float4*>(
                &basis[row * INF + k0 + c4 * 4]);
            float* d = &bs[row * 33 + c4 * 4];
            d[0] = v.x; d[1] = v.y; d[2] = v.z; d[3] = v.w;
        }
        __syncthreads();
#pragma unroll
        for (int kk = 0; kk < 32; kk++) {
            float a[4], b[4];
#pragma unroll
            for (int i = 0; i < 4; i++) a[i] = xs[(tg * 4 + i) * 33 + kk];
#pragma unroll
            for (int j = 0; j < 4; j++) b[j] = bs[(hg * 4 + j) * 33 + kk];
#pragma unroll
            for (int i = 0; i < 4; i++)
#pragma unroll
                for (int j = 0; j < 4; j++)
                    acc[i][j] = fmaf(a[i], b[j], acc[i][j]);
        }
    }
#pragma unroll
    for (int i = 0; i < 4; i++) {
        long t = tb + tg * 4 + i;
#pragma unroll
        for (int j = 0; j < 4; j++) {
            int h = hg * 4 + j;
            float v = acc[i][j];
            __nv_bfloat16 hi = __float2bfloat16(v);
            __nv_bfloat16 lo = __float2bfloat16(v - __bfloat162float(hi));
            g_Rs[t * KSPL + h]      = hi;
            g_Rs[t * KSPL + 32 + h] = lo;
            g_Rs[t * KSPL + 64 + h] = hi;
        }
    }
}

// ---------------------------------------------------------------------------
// Step 3: out = A @ B^T via mma.sync m16n8k16 bf16 (fp32 acc).
// CTA tile 128 tokens x 128 outputs, K=96 resident. 8 warps = 2(m) x 4(n),
// warp tile 64x32. Smem rows padded to 240B (conflict-free ldmatrix).
// ---------------------------------------------------------------------------
#define SA_BYTES (128 * KPAD * 2)            // 30720
#define SM3_TOTAL (2 * SA_BYTES)             // 61440

__global__ __launch_bounds__(256) void holo_hmma_kernel(float* __restrict__ out) {
    extern __shared__ char smem[];
    __nv_bfloat16* sA = reinterpret_cast<__nv_bfloat16*>(smem);
    __nv_bfloat16* sB = reinterpret_cast<__nv_bfloat16*>(smem + SA_BYTES);

    int tid  = threadIdx.x;
    int lane = tid & 31;
    int wid  = tid >> 5;
    int warp_m = wid >> 2;   // 0..1 -> 64 rows
    int warp_n = wid & 3;    // 0..3 -> 32 cols

    int ob = blockIdx.x * 128;
    int tb = blockIdx.y * 128;

    // Global -> smem: 128 rows x 96 bf16 (12 uint4/row), both tiles.
    const uint4* gA = reinterpret_cast<const uint4*>(&g_Rs[(long)tb * KSPL]);
    const uint4* gB = reinterpret_cast<const uint4*>(&g_Ws[(long)ob * KSPL]);
#pragma unroll
    for (int r = 0; r < 6; r++) {
        int q = tid + r * 256;         // 0..1535
        int row = q / 12;
        int ch  = q - row * 12;        // 16B chunk
        uint32_t soff = (uint32_t)row * (KPAD * 2) + ch * 16;
        *reinterpret_cast<uint4*>(reinterpret_cast<char*>(sA) + soff) = gA[q];
        *reinterpret_cast<uint4*>(reinterpret_cast<char*>(sB) + soff) = gB[q];
    }
    __syncthreads();

    uint32_t sAb = smem_u32(sA);
    uint32_t sBb = smem_u32(sB);

    float acc[4][4][4];   // [mtile][ntile][frag]
#pragma unroll
    for (int i = 0; i < 4; i++)
#pragma unroll
        for (int j = 0; j < 4; j++)
#pragma unroll
            for (int c = 0; c < 4; c++) acc[i][j][c] = 0.0f;

#pragma unroll
    for (int ks = 0; ks < 6; ks++) {
        int k0 = ks * 16;
        // A fragments: 4 mtiles of 16 rows
        uint32_t af[4][4];
#pragma unroll
        for (int i = 0; i < 4; i++) {
            int row = warp_m * 64 + i * 16 + (lane & 15);
            uint32_t addr = sAb + (uint32_t)row * (KPAD * 2) + k0 * 2 + (lane >> 4) * 16;
            asm volatile(
                "ldmatrix.sync.aligned.m8n8.x4.shared.b16 {%0,%1,%2,%3}, [%4];"
                : "=r"(af[i][0]), "=r"(af[i][1]), "=r"(af[i][2]), "=r"(af[i][3])
                : "r"(addr));
        }
        // B fragments: 4 ntiles of 8 cols
        uint32_t bf[4][2];
#pragma unroll
        for (int j = 0; j < 4; j++) {
            int nrow = warp_n * 32 + j * 8 + (lane & 7);
            uint32_t addr = sBb + (uint32_t)nrow * (KPAD * 2) + k0 * 2 + ((lane >> 3) & 1) * 16;
            asm volatile(
                "ldmatrix.sync.aligned.m8n8.x2.shared.b16 {%0,%1}, [%2];"
                : "=r"(bf[j][0]), "=r"(bf[j][1])
                : "r"(addr));
        }
#pragma unroll
        for (int i = 0; i < 4; i++)
#pragma unroll
            for (int j = 0; j < 4; j++) {
                asm volatile(
                    "mma.sync.aligned.m16n8k16.row.col.f32.bf16.bf16.f32 "
                    "{%0,%1,%2,%3}, {%4,%5,%6,%7}, {%8,%9}, {%0,%1,%2,%3};"
                    : "+f"(acc[i][j][0]), "+f"(acc[i][j][1]),
                      "+f"(acc[i][j][2]), "+f"(acc[i][j][3])
                    : "r"(af[i][0]), "r"(af[i][1]), "r"(af[i][2]), "r"(af[i][3]),
                      "r"(bf[j][0]), "r"(bf[j][1]));
            }
    }

    // Epilogue: direct float2 stores from C fragments.
    int qrow = lane >> 2;          // 0..7
    int qcol = (lane & 3) * 2;     // 0,2,4,6
#pragma unroll
    for (int i = 0; i < 4; i++) {
        long r0 = tb + warp_m * 64 + i * 16 + qrow;
#pragma unroll
        for (int j = 0; j < 4; j++) {
            long c = ob + warp_n * 32 + j * 8 + qcol;
            *reinterpret_cast<float2*>(&out[r0 * OUTF + c]) =
                make_float2(acc[i][j][0], acc[i][j][1]);
            *reinterpret_cast<float2*>(&out[(r0 + 8) * OUTF + c]) =
                make_float2(acc[i][j][2], acc[i][j][3]);
        }
    }
}

// ---------------------------------------------------------------------------
extern "C" void kernel_launch(void* const* d_in, const int* in_sizes, int n_in,
                              void* d_out, int out_size) {
    const float* x     = (const float*)d_in[0];  // [16384,1024]
    const float* basis = (const float*)d_in[1];  // [32,1024]
    const float* phase = (const float*)d_in[2];  // [4096,32]
    const float* amp   = (const float*)d_in[3];  // [4096,32]
    float* out = (float*)d_out;                  // [16384,4096]

    cudaFuncSetAttribute(holo_hmma_kernel,
                         cudaFuncAttributeMaxDynamicSharedMemorySize, SM3_TOTAL);

    prep_w_kernel<<<(OUTF * HARM) / 256, 256>>>(phase, amp);
    resonance_kernel<<<TOKENS / 128, 256>>>(x, basis);
    dim3 gridC(OUTF / 128, TOKENS / 128);
    holo_hmma_kernel<<<gridC, 256, SM3_TOTAL>>>(out);
}

// round 4
// speedup vs baseline: 1.9232x; 1.3769x over previous
#include <cuda_runtime.h>
#include <cuda_bf16.h>
#include <cstdint>

// out[t][o] = sum_h R[t][h] * W[o][h],  R = x @ basis^T, W = amp*cos(phase)
// Both GEMMs on HMMA (mma.sync bf16) with 3-term split precision:
//   step2: A=[x_hi | x_lo | x_hi], B=[b_hi | b_hi | b_lo]  (per K-chunk)
//   step3: A=[R_hi | R_lo | R_hi] (K=96), B=[W_hi | W_hi | W_lo]
#define TOKENS 16384
#define INF    1024
#define HARM   32
#define OUTF   4096
#define KSPL   96
#define KPAD   120   // step-3 smem row stride in bf16 (240 B)

// Scratch device globals
__device__ __align__(16) __nv_bfloat16 g_Rs[TOKENS * KSPL];  // 3 MB   [t][hi|lo|hi]
__device__ __align__(16) __nv_bfloat16 g_Ws[OUTF * KSPL];    // 768 KB [o][hi|hi|lo]
__device__ __align__(16) __nv_bfloat16 g_Bh[HARM * INF];     // 64 KB  basis hi
__device__ __align__(16) __nv_bfloat16 g_Bl[HARM * INF];     // 64 KB  basis lo

__device__ __forceinline__ uint32_t smem_u32(const void* p) {
    uint32_t a;
    asm("{ .reg .u64 t; cvta.to.shared.u64 t, %1; cvt.u32.u64 %0, t; }"
        : "=r"(a) : "l"(p));
    return a;
}
__device__ __forceinline__ uint32_t pack_bf2(__nv_bfloat16 a, __nv_bfloat16 b) {
    return (uint32_t)__bfloat16_as_ushort(a) |
           ((uint32_t)__bfloat16_as_ushort(b) << 16);
}

// ---------------------------------------------------------------------------
// Prep: W = amp*cos(phase) split [o][hi|hi|lo]; basis split hi/lo.
// ---------------------------------------------------------------------------
__global__ void prep_kernel(const float* __restrict__ phase,
                            const float* __restrict__ amp,
                            const float* __restrict__ basis) {
    int idx = blockIdx.x * 256 + threadIdx.x;
    if (idx < OUTF * HARM) {
        int o = idx >> 5;
        int h = idx & 31;
        float w = amp[idx] * cosf(phase[idx]);
        __nv_bfloat16 hi = __float2bfloat16(w);
        __nv_bfloat16 lo = __float2bfloat16(w - __bfloat162float(hi));
        g_Ws[o * KSPL + h]      = hi;
        g_Ws[o * KSPL + 32 + h] = hi;
        g_Ws[o * KSPL + 64 + h] = lo;
    } else {
        int b = idx - OUTF * HARM;
        if (b < HARM * INF) {
            float v = basis[b];
            __nv_bfloat16 hi = __float2bfloat16(v);
            __nv_bfloat16 lo = __float2bfloat16(v - __bfloat162float(hi));
            g_Bh[b] = hi;
            g_Bl[b] = lo;
        }
    }
}

// ---------------------------------------------------------------------------
// Step 2: R = x @ basis^T via HMMA.  256 CTAs x 128 threads (4 warps).
// Tile: 64 tokens x 32 harmonics, K chunks of 64 fp32 (16 chunks), 3-term bf16.
// Epilogue writes g_Rs split [t][hi|lo|hi].
// Smem rows padded to 72 bf16 (144 B) -> conflict-free ldmatrix.
// ---------------------------------------------------------------------------
#define RKC 64
#define RPAD 72
__global__ __launch_bounds__(128) void resonance_hmma_kernel(
    const float* __restrict__ x) {
    __shared__ __nv_bfloat16 sxh[64 * RPAD];   // 9.2 KB
    __shared__ __nv_bfloat16 sxl[64 * RPAD];
    __shared__ __nv_bfloat16 sbh[32 * RPAD];   // 4.6 KB
    __shared__ __nv_bfloat16 sbl[32 * RPAD];

    int tid  = threadIdx.x;
    int lane = tid & 31;
    int wid  = tid >> 5;        // 0..3 -> 16-row mtile
    int tb   = blockIdx.x * 64;

    uint32_t sxh_b = smem_u32(sxh), sxl_b = smem_u32(sxl);
    uint32_t sbh_b = smem_u32(sbh), sbl_b = smem_u32(sbl);

    float acc[4][4];
#pragma unroll
    for (int j = 0; j < 4; j++)
#pragma unroll
        for (int c = 0; c < 4; c++) acc[j][c] = 0.0f;

    // prefetch chunk 0
    float4 xp[8];
    uint4  bhp[2], blp[2];
    {
        const float4* gx = reinterpret_cast<const float4*>(x);
#pragma unroll
        for (int r = 0; r < 8; r++) {
            int q = tid + r * 128;          // 0..1023
            int row = q >> 4, c4 = q & 15;
            xp[r] = gx[(long)(tb + row) * (INF / 4) + c4];
        }
        const uint4* gbh = reinterpret_cast<const uint4*>(g_Bh);
        const uint4* gbl = reinterpret_cast<const uint4*>(g_Bl);
#pragma unroll
        for (int r = 0; r < 2; r++) {
            int q = tid + r * 128;          // 0..255
            int row = q >> 3, c4 = q & 7;
            bhp[r] = gbh[row * (INF / 8) + c4];
            blp[r] = gbl[row * (INF / 8) + c4];
        }
    }

    for (int ck = 0; ck < 16; ck++) {
        if (ck > 0) __syncthreads();
        // convert + store x chunk
#pragma unroll
        for (int r = 0; r < 8; r++) {
            int q = tid + r * 128;
            int row = q >> 4, c4 = q & 15;
            float4 v = xp[r];
            __nv_bfloat16 h0 = __float2bfloat16(v.x);
            __nv_bfloat16 h1 = __float2bfloat16(v.y);
            __nv_bfloat16 h2 = __float2bfloat16(v.z);
            __nv_bfloat16 h3 = __float2bfloat16(v.w);
            uint2 hp = make_uint2(pack_bf2(h0, h1), pack_bf2(h2, h3));
            uint2 lp = make_uint2(
                pack_bf2(__float2bfloat16(v.x - __bfloat162float(h0)),
                         __float2bfloat16(v.y - __bfloat162float(h1))),
                pack_bf2(__float2bfloat16(v.z - __bfloat162float(h2)),
                         __float2bfloat16(v.w - __bfloat162float(h3))));
            int off = row * RPAD + c4 * 4;
            *reinterpret_cast<uint2*>(&sxh[off]) = hp;
            *reinterpret_cast<uint2*>(&sxl[off]) = lp;
        }
        // store basis chunk
#pragma unroll
        for (int r = 0; r < 2; r++) {
            int q = tid + r * 128;
            int row = q >> 3, c4 = q & 7;
            int off = row * RPAD + c4 * 8;
            *reinterpret_cast<uint4*>(&sbh[off]) = bhp[r];
            *reinterpret_cast<uint4*>(&sbl[off]) = blp[r];
        }
        __syncthreads();

        // prefetch next chunk while mma runs
        if (ck < 15) {
            int kc = (ck + 1) * RKC;
            const float4* gx = reinterpret_cast<const float4*>(x);
#pragma unroll
            for (int r = 0; r < 8; r++) {
                int q = tid + r * 128;
                int row = q >> 4, c4 = q & 15;
                xp[r] = gx[(long)(tb + row) * (INF / 4) + kc / 4 + c4];
            }
            const uint4* gbh = reinterpret_cast<const uint4*>(g_Bh);
            const uint4* gbl = reinterpret_cast<const uint4*>(g_Bl);
#pragma unroll
            for (int r = 0; r < 2; r++) {
                int q = tid + r * 128;
                int row = q >> 3, c4 = q & 7;
                bhp[r] = gbh[row * (INF / 8) + kc / 8 + c4];
                blp[r] = gbl[row * (INF / 8) + kc / 8 + c4];
            }
        }

#pragma unroll
        for (int ks = 0; ks < 4; ks++) {
            int k0 = ks * 16;
            uint32_t ah[4], al[4];
            {
                int row = wid * 16 + (lane & 15);
                uint32_t ao = (uint32_t)row * (RPAD * 2) + k0 * 2 + (lane >> 4) * 16;
                asm volatile(
                    "ldmatrix.sync.aligned.m8n8.x4.shared.b16 {%0,%1,%2,%3}, [%4];"
                    : "=r"(ah[0]), "=r"(ah[1]), "=r"(ah[2]), "=r"(ah[3])
                    : "r"(sxh_b + ao));
                asm volatile(
                    "ldmatrix.sync.aligned.m8n8.x4.shared.b16 {%0,%1,%2,%3}, [%4];"
                    : "=r"(al[0]), "=r"(al[1]), "=r"(al[2]), "=r"(al[3])
                    : "r"(sxl_b + ao));
            }
#pragma unroll
            for (int j = 0; j < 4; j++) {
                int nrow = j * 8 + (lane & 7);
                uint32_t bo = (uint32_t)nrow * (RPAD * 2) + k0 * 2 + ((lane >> 3) & 1) * 16;
                uint32_t bh[2], bl[2];
                asm volatile(
                    "ldmatrix.sync.aligned.m8n8.x2.shared.b16 {%0,%1}, [%2];"
                    : "=r"(bh[0]), "=r"(bh[1]) : "r"(sbh_b + bo));
                asm volatile(
                    "ldmatrix.sync.aligned.m8n8.x2.shared.b16 {%0,%1}, [%2];"
                    : "=r"(bl[0]), "=r"(bl[1]) : "r"(sbl_b + bo));
                asm volatile(
                    "mma.sync.aligned.m16n8k16.row.col.f32.bf16.bf16.f32 "
                    "{%0,%1,%2,%3}, {%4,%5,%6,%7}, {%8,%9}, {%0,%1,%2,%3};"
                    : "+f"(acc[j][0]), "+f"(acc[j][1]), "+f"(acc[j][2]), "+f"(acc[j][3])
                    : "r"(ah[0]), "r"(ah[1]), "r"(ah[2]), "r"(ah[3]),
                      "r"(bh[0]), "r"(bh[1]));
                asm volatile(
                    "mma.sync.aligned.m16n8k16.row.col.f32.bf16.bf16.f32 "
                    "{%0,%1,%2,%3}, {%4,%5,%6,%7}, {%8,%9}, {%0,%1,%2,%3};"
                    : "+f"(acc[j][0]), "+f"(acc[j][1]), "+f"(acc[j][2]), "+f"(acc[j][3])
                    : "r"(al[0]), "r"(al[1]), "r"(al[2]), "r"(al[3]),
                      "r"(bh[0]), "r"(bh[1]));
                asm volatile(
                    "mma.sync.aligned.m16n8k16.row.col.f32.bf16.bf16.f32 "
                    "{%0,%1,%2,%3}, {%4,%5,%6,%7}, {%8,%9}, {%0,%1,%2,%3};"
                    : "+f"(acc[j][0]), "+f"(acc[j][1]), "+f"(acc[j][2]), "+f"(acc[j][3])
                    : "r"(ah[0]), "r"(ah[1]), "r"(ah[2]), "r"(ah[3]),
                      "r"(bl[0]), "r"(bl[1]));
            }
        }
    }

    // Epilogue: write split R [t][hi(0:32)|lo(32:64)|hi(64:96)] as u32 pairs.
    uint32_t* gR32 = reinterpret_cast<uint32_t*>(g_Rs);
    int qrow = lane >> 2;
    int qcol = (lane & 3) * 2;
#pragma unroll
    for (int j = 0; j < 4; j++) {
        int wc = (j * 8 + qcol) >> 1;   // u32 index 0..15
#pragma unroll
        for (int hh = 0; hh < 2; hh++) {
            long t = tb + wid * 16 + qrow + hh * 8;
            float v0 = acc[j][hh * 2 + 0];
            float v1 = acc[j][hh * 2 + 1];
            __nv_bfloat16 h0 = __float2bfloat16(v0);
            __nv_bfloat16 h1 = __float2bfloat16(v1);
            uint32_t hip = pack_bf2(h0, h1);
            uint32_t lop = pack_bf2(
                __float2bfloat16(v0 - __bfloat162float(h0)),
                __float2bfloat16(v1 - __bfloat162float(h1)));
            long base = t * (KSPL / 2);
            gR32[base + wc]      = hip;
            gR32[base + 16 + wc] = lop;
            gR32[base + 32 + wc] = hip;
        }
    }
}

// ---------------------------------------------------------------------------
// Step 3: out = A @ B^T via HMMA. CTA 128x128, K=96, 8 warps = 2(m) x 4(n),
// warp tile 64x32. Per-warp smem-staged epilogue -> STG.128 full lines.
// ---------------------------------------------------------------------------
#define SA_BYTES (128 * KPAD * 2)            // 30720
#define SM3_TOTAL (2 * SA_BYTES)             // 61440 dynamic
#define WSTRIDE 40

__global__ __launch_bounds__(256) void holo_hmma_kernel(float* __restrict__ out) {
    extern __shared__ char smem[];
    __shared__ float wstage[8][16 * WSTRIDE];   // 20.5 KB static
    __nv_bfloat16* sA = reinterpret_cast<__nv_bfloat16*>(smem);
    __nv_bfloat16* sB = reinterpret_cast<__nv_bfloat16*>(smem + SA_BYTES);

    int tid  = threadIdx.x;
    int lane = tid & 31;
    int wid  = tid >> 5;
    int warp_m = wid >> 2;   // 0..1
    int warp_n = wid & 3;    // 0..3

    int ob = blockIdx.x * 128;
    int tb = blockIdx.y * 128;

    const uint4* gA = reinterpret_cast<const uint4*>(&g_Rs[(long)tb * KSPL]);
    const uint4* gB = reinterpret_cast<const uint4*>(&g_Ws[(long)ob * KSPL]);
#pragma unroll
    for (int r = 0; r < 6; r++) {
        int q = tid + r * 256;         // 0..1535
        int row = q / 12;
        int ch  = q - row * 12;
        uint32_t soff = (uint32_t)row * (KPAD * 2) + ch * 16;
        *reinterpret_cast<uint4*>(reinterpret_cast<char*>(sA) + soff) = gA[q];
        *reinterpret_cast<uint4*>(reinterpret_cast<char*>(sB) + soff) = gB[q];
    }
    __syncthreads();

    uint32_t sAb = smem_u32(sA);
    uint32_t sBb = smem_u32(sB);

    float acc[4][4][4];
#pragma unroll
    for (int i = 0; i < 4; i++)
#pragma unroll
        for (int j = 0; j < 4; j++)
#pragma unroll
            for (int c = 0; c < 4; c++) acc[i][j][c] = 0.0f;

#pragma unroll
    for (int ks = 0; ks < 6; ks++) {
        int k0 = ks * 16;
        uint32_t af[4][4];
#pragma unroll
        for (int i = 0; i < 4; i++) {
            int row = warp_m * 64 + i * 16 + (lane & 15);
            uint32_t addr = sAb + (uint32_t)row * (KPAD * 2) + k0 * 2 + (lane >> 4) * 16;
            asm volatile(
                "ldmatrix.sync.aligned.m8n8.x4.shared.b16 {%0,%1,%2,%3}, [%4];"
                : "=r"(af[i][0]), "=r"(af[i][1]), "=r"(af[i][2]), "=r"(af[i][3])
                : "r"(addr));
        }
        uint32_t bf[4][2];
#pragma unroll
        for (int j = 0; j < 4; j++) {
            int nrow = warp_n * 32 + j * 8 + (lane & 7);
            uint32_t addr = sBb + (uint32_t)nrow * (KPAD * 2) + k0 * 2 + ((lane >> 3) & 1) * 16;
            asm volatile(
                "ldmatrix.sync.aligned.m8n8.x2.shared.b16 {%0,%1}, [%2];"
                : "=r"(bf[j][0]), "=r"(bf[j][1])
                : "r"(addr));
        }
#pragma unroll
        for (int i = 0; i < 4; i++)
#pragma unroll
            for (int j = 0; j < 4; j++) {
                asm volatile(
                    "mma.sync.aligned.m16n8k16.row.col.f32.bf16.bf16.f32 "
                    "{%0,%1,%2,%3}, {%4,%5,%6,%7}, {%8,%9}, {%0,%1,%2,%3};"
                    : "+f"(acc[i][j][0]), "+f"(acc[i][j][1]),
                      "+f"(acc[i][j][2]), "+f"(acc[i][j][3])
                    : "r"(af[i][0]), "r"(af[i][1]), "r"(af[i][2]), "r"(af[i][3]),
                      "r"(bf[j][0]), "r"(bf[j][1]));
            }
    }

    // Staged epilogue: per-warp 16x32 tile through smem -> coalesced STG.128.
    int qrow = lane >> 2;
    int qcol = (lane & 3) * 2;
    float* wb = wstage[wid];
#pragma unroll
    for (int i = 0; i < 4; i++) {
#pragma unroll
        for (int j = 0; j < 4; j++) {
            *reinterpret_cast<float2*>(&wb[qrow * WSTRIDE + j * 8 + qcol]) =
                make_float2(acc[i][j][0], acc[i][j][1]);
            *reinterpret_cast<float2*>(&wb[(qrow + 8) * WSTRIDE + j * 8 + qcol]) =
                make_float2(acc[i][j][2], acc[i][j][3]);
        }
        __syncwarp();
        long r0 = tb + warp_m * 64 + i * 16;
        long c0 = ob + warp_n * 32;
#pragma unroll
        for (int s = 0; s < 4; s++) {
            int q = lane + s * 32;       // 0..127
            int row = q >> 3, c4 = q & 7;
            float4 v = *reinterpret_cast<float4*>(&wb[row * WSTRIDE + c4 * 4]);
            *reinterpret_cast<float4*>(&out[(r0 + row) * OUTF + c0 + c4 * 4]) = v;
        }
        __syncwarp();
    }
}

// ---------------------------------------------------------------------------
extern "C" void kernel_launch(void* const* d_in, const int* in_sizes, int n_in,
                              void* d_out, int out_size) {
    const float* x     = (const float*)d_in[0];  // [16384,1024]
    const float* basis = (const float*)d_in[1];  // [32,1024]
    const float* phase = (const float*)d_in[2];  // [4096,32]
    const float* amp   = (const float*)d_in[3];  // [4096,32]
    float* out = (float*)d_out;                  // [16384,4096]

    cudaFuncSetAttribute(holo_hmma_kernel,
                         cudaFuncAttributeMaxDynamicSharedMemorySize, SM3_TOTAL);

    int prep_items = OUTF * HARM + HARM * INF;
    prep_kernel<<<(prep_items + 255) / 256, 256>>>(phase, amp, basis);
    resonance_hmma_kernel<<<TOKENS / 64, 128>>>(x);
    dim3 gridC(OUTF / 128, TOKENS / 128);
    holo_hmma_kernel<<<gridC, 256, SM3_TOTAL>>>(out);
}